// round 4
// baseline (speedup 1.0000x reference)
#include <cuda_runtime.h>
#include <cstdint>

// ---------------------------------------------------------------------------
// TreeRNN: complete binary tree LSTM over 128 leaves, batch 512, hidden 256.
//
// Pipeline per launch:
//   gather  : emb/emb_aux lookups -> leaves, leaves_aux, leaf slots of
//             internal_states (post-order), and level-0 paired h buffer.
//   masks   : fill internal_mask + leaves_mask with 1.0f.
//   7x level: GEMM (M x 512 @ 512 x 1280 -> G scratch), then gates kernel
//             (bias + LSTM gates -> h,c; writes internal_states post-order,
//              next-level paired h/c buffers, and root at the last level).
//
// Paired layout trick: level-l h is stored as [pair][b][512] with the left
// child in cols [0,256) and right child in [256,512), so the concat(hL,hR)
// row of the next GEMM is contiguous -> plain row-major A.
// ---------------------------------------------------------------------------

#define Hd   256
#define Bt   512
#define Lf   128
#define K2   512      // 2*H
#define N5   1280     // 5*H
#define NLEV 7        // log2(Lf)

// Output buffer layout (flattened fp32, reference return order)
#define OFF_ROOT   0
#define OFF_INT    (Bt * Hd)                               // 131072
#define OFF_IMASK  (OFF_INT + 255 * Bt * Hd)               // 33554432
#define OFF_LEAVES (OFF_IMASK + 255 * Bt)                  // 33684992
#define OFF_LAUX   (OFF_LEAVES + Lf * Bt * Hd)             // 50462208
#define OFF_LMASK  (OFF_LAUX + Lf * Bt * Hd)               // 67239424
// OFF_LMASK + Lf*Bt = 67304960 == out_size

// Scratch (device globals; no runtime allocation allowed)
__device__ float g_A[2][64 * Bt * K2];   // paired h, ping-pong   (2 x 67 MB)
__device__ float g_C[2][32 * Bt * K2];   // paired c, ping-pong   (2 x 34 MB)
__device__ float g_G[32768 * N5];        // gate pre-activations  (168 MB)

// Post-order index of node (level, j); level 0 = leaves, level 7 = root.
// post_idx = (2^(l+1)-2) + sum over right-turns on root path of left-subtree
// sizes. Verified: leaf0->0, leaf1->1, leaf2->3, L1 j=0 -> 2, L1 j=1 -> 5,
// root -> 254.
__device__ __forceinline__ int post_idx(int level, int j) {
    int start = (1 << (level + 1)) - 2;
    for (int m = level + 1; m <= NLEV; ++m)
        start += ((j >> (m - 1 - level)) & 1) ? ((1 << m) - 1) : 0;
    return start;
}

__device__ __forceinline__ float sigf(float x) {
    return 1.0f / (1.0f + __expf(-x));
}

// ---------------------------------------------------------------------------
// Gather: leaves, leaves_aux, leaf internal_states, level-0 paired buffer
// ---------------------------------------------------------------------------
__global__ void gather_kernel(const int* __restrict__ tok,
                              const float4* __restrict__ emb,
                              const float4* __restrict__ emb_aux,
                              float* __restrict__ out) {
    int idx = blockIdx.x * blockDim.x + threadIdx.x;   // Lf*Bt*(Hd/4) = 4194304
    if (idx >= Lf * Bt * (Hd / 4)) return;
    const int hc4 = idx & 63;
    const int b   = (idx >> 6) & (Bt - 1);
    const int j   = idx >> 15;

    const int t = tok[j * Bt + b];
    const float4 v  = emb[t * (Hd / 4) + hc4];
    const float4 va = emb_aux[t * (Hd / 4) + hc4];

    ((float4*)(out + OFF_LEAVES))[idx] = v;
    ((float4*)(out + OFF_LAUX))[idx]   = va;

    const int p = post_idx(0, j);
    ((float4*)(out + OFF_INT + ((size_t)p * Bt + b) * Hd))[hc4] = v;

    const size_t dst = (((size_t)(j >> 1) * Bt + b) * K2) + (j & 1) * Hd;
    ((float4*)(&g_A[0][dst]))[hc4] = v;
}

// ---------------------------------------------------------------------------
// Masks: all trees full length -> all True (1.0f)
// ---------------------------------------------------------------------------
__global__ void mask_kernel(float* __restrict__ out) {
    int idx = blockIdx.x * blockDim.x + threadIdx.x;
    const int NI = 255 * Bt;          // 130560
    const int NL = Lf * Bt;           // 65536
    if (idx < NI)            out[OFF_IMASK + idx] = 1.0f;
    else if (idx < NI + NL)  out[OFF_LMASK + (idx - NI)] = 1.0f;
}

// ---------------------------------------------------------------------------
// SGEMM: G[M,1280] = A[M,512] @ W[512,1280]  (A = g_A[cur], row-major)
// 128x128 tile, BK=16, 256 threads, 8x8 micro-tile, DOUBLE-BUFFERED smem:
// next tile's GMEM loads are issued into registers before the FMA block and
// committed to the alternate buffer after, so the 234-577 cyc load latency
// is hidden behind the 1024 FFMA instrs/thread per K-step. One bar.sync per
// K-step. M is a multiple of 128; K,N tile exactly -> no bounds checks.
// ---------------------------------------------------------------------------
#define BM 128
#define BN 128
#define BK 16

__global__ void __launch_bounds__(256, 2)
gemm_kernel(const float* __restrict__ Wm, int M, int cur) {
    __shared__ float As[2][BK][BM + 4];   // transposed A tile, padded
    __shared__ float Bs[2][BK][BN];

    const float* __restrict__ A = g_A[cur];
    const int bn = blockIdx.x * BN;
    const int bm = blockIdx.y * BM;
    const int tid = threadIdx.x;
    const int tx = tid & 15;
    const int ty = tid >> 4;

    // loader indices
    const int aRow  = tid >> 2;   // 0..63 (two iters cover 128 rows)
    const int aCol4 = tid & 3;    // float4 index along K
    const int bRow  = tid >> 5;   // 0..7  (two iters cover 16 rows)
    const int bCol4 = tid & 31;   // float4 index along N

    const float* __restrict__ aPtr = A  + (size_t)(bm + aRow) * K2 + aCol4 * 4;
    const float* __restrict__ bPtr = Wm + (size_t)bRow * N5 + bn + bCol4 * 4;

    float acc[8][8];
#pragma unroll
    for (int i = 0; i < 8; i++)
#pragma unroll
        for (int j = 0; j < 8; j++) acc[i][j] = 0.0f;

    // ---- prologue: load tile k0=0 into buffer 0 ----
    float4 aFrag[2], bFrag[2];
#pragma unroll
    for (int it = 0; it < 2; it++) {
        aFrag[it] = *(const float4*)(aPtr + (size_t)(it * 64) * K2);
        bFrag[it] = *(const float4*)(bPtr + (size_t)(it * 8) * N5);
    }
#pragma unroll
    for (int it = 0; it < 2; it++) {
        int r = aRow + it * 64;
        As[0][aCol4 * 4 + 0][r] = aFrag[it].x;
        As[0][aCol4 * 4 + 1][r] = aFrag[it].y;
        As[0][aCol4 * 4 + 2][r] = aFrag[it].z;
        As[0][aCol4 * 4 + 3][r] = aFrag[it].w;
        *(float4*)(&Bs[0][bRow + it * 8][bCol4 * 4]) = bFrag[it];
    }
    __syncthreads();

    int buf = 0;
    for (int k0 = 0; k0 < K2; k0 += BK) {
        const bool hasNext = (k0 + BK) < K2;
        // issue next tile's global loads early (latency hidden by FMAs below)
        if (hasNext) {
#pragma unroll
            for (int it = 0; it < 2; it++) {
                aFrag[it] = *(const float4*)(aPtr + (size_t)(it * 64) * K2 + (k0 + BK));
                bFrag[it] = *(const float4*)(bPtr + (size_t)(it * 8 + k0 + BK) * N5);
            }
        }

        // compute on current buffer
#pragma unroll
        for (int k = 0; k < BK; ++k) {
            float4 a0 = *(const float4*)(&As[buf][k][ty * 4]);
            float4 a1 = *(const float4*)(&As[buf][k][64 + ty * 4]);
            float4 b0 = *(const float4*)(&Bs[buf][k][tx * 4]);
            float4 b1 = *(const float4*)(&Bs[buf][k][64 + tx * 4]);
            float ar[8] = {a0.x, a0.y, a0.z, a0.w, a1.x, a1.y, a1.z, a1.w};
            float br[8] = {b0.x, b0.y, b0.z, b0.w, b1.x, b1.y, b1.z, b1.w};
#pragma unroll
            for (int i = 0; i < 8; i++)
#pragma unroll
                for (int j = 0; j < 8; j++)
                    acc[i][j] += ar[i] * br[j];
        }

        // commit prefetched tile to the other buffer
        if (hasNext) {
            const int nb = buf ^ 1;
#pragma unroll
            for (int it = 0; it < 2; it++) {
                int r = aRow + it * 64;
                As[nb][aCol4 * 4 + 0][r] = aFrag[it].x;
                As[nb][aCol4 * 4 + 1][r] = aFrag[it].y;
                As[nb][aCol4 * 4 + 2][r] = aFrag[it].z;
                As[nb][aCol4 * 4 + 3][r] = aFrag[it].w;
                *(float4*)(&Bs[nb][bRow + it * 8][bCol4 * 4]) = bFrag[it];
            }
            __syncthreads();
            buf = nb;
        }
    }

#pragma unroll
    for (int ih = 0; ih < 2; ih++)
#pragma unroll
        for (int ii = 0; ii < 4; ii++) {
            const int r = bm + ih * 64 + ty * 4 + ii;
            float* __restrict__ grow = g_G + (size_t)r * N5 + bn;
#pragma unroll
            for (int jh = 0; jh < 2; jh++) {
                const int ai = ih * 4 + ii;
                float4 v = make_float4(acc[ai][jh * 4 + 0], acc[ai][jh * 4 + 1],
                                       acc[ai][jh * 4 + 2], acc[ai][jh * 4 + 3]);
                *(float4*)(grow + jh * 64 + tx * 4) = v;
            }
        }
}

// ---------------------------------------------------------------------------
// Gates (float4 lanes): bias + LSTM combine; writes internal_states
// (post-order), next-level paired h/c buffers, and root at the final level.
// One thread = 4 hidden columns -> 16B coalesced LDG/STG throughout.
// ---------------------------------------------------------------------------
__global__ void gates_kernel(const float4* __restrict__ bias4,
                             float* __restrict__ out,
                             int level, int n2, int cur) {
    int idx = blockIdx.x * blockDim.x + threadIdx.x;
    if (idx >= (n2 << 15)) return;           // n2 * Bt * (Hd/4)
    const int hc4 = idx & 63;                // float4 index within H
    const int b   = (idx >> 6) & (Bt - 1);
    const int q   = idx >> 15;

    const float4* __restrict__ g4 = (const float4*)(g_G + ((size_t)q * Bt + b) * N5);
    const float4 gi  = g4[hc4];
    const float4 gf1 = g4[64  + hc4];
    const float4 gf2 = g4[128 + hc4];
    const float4 go  = g4[192 + hc4];
    const float4 gu  = g4[256 + hc4];
    const float4 bi  = bias4[hc4];
    const float4 bf1 = bias4[64  + hc4];
    const float4 bf2 = bias4[128 + hc4];
    const float4 bo  = bias4[192 + hc4];
    const float4 bu  = bias4[256 + hc4];

    float4 cL = make_float4(0.f, 0.f, 0.f, 0.f);
    float4 cR = cL;
    if (level > 0) {
        const float4* __restrict__ C4 =
            (const float4*)(g_C[cur] + ((size_t)q * Bt + b) * K2);
        cL = C4[hc4];
        cR = C4[64 + hc4];
    }

    float4 h4, c4;
    {
        float i_[4]  = {gi.x + bi.x,  gi.y + bi.y,  gi.z + bi.z,  gi.w + bi.w};
        float f1[4]  = {gf1.x + bf1.x, gf1.y + bf1.y, gf1.z + bf1.z, gf1.w + bf1.w};
        float f2[4]  = {gf2.x + bf2.x, gf2.y + bf2.y, gf2.z + bf2.z, gf2.w + bf2.w};
        float o_[4]  = {go.x + bo.x,  go.y + bo.y,  go.z + bo.z,  go.w + bo.w};
        float u_[4]  = {gu.x + bu.x,  gu.y + bu.y,  gu.z + bu.z,  gu.w + bu.w};
        float cl[4]  = {cL.x, cL.y, cL.z, cL.w};
        float cr[4]  = {cR.x, cR.y, cR.z, cR.w};
        float hv[4], cv[4];
#pragma unroll
        for (int e = 0; e < 4; e++) {
            float c = sigf(i_[e]) * tanhf(u_[e]);
            if (level > 0)
                c += sigf(f1[e]) * cl[e] + sigf(f2[e]) * cr[e];
            hv[e] = sigf(o_[e]) * tanhf(c);
            cv[e] = c;
        }
        h4 = make_float4(hv[0], hv[1], hv[2], hv[3]);
        c4 = make_float4(cv[0], cv[1], cv[2], cv[3]);
    }

    const int outlev = level + 1;
    const int p = post_idx(outlev, q);
    ((float4*)(out + OFF_INT + ((size_t)p * Bt + b) * Hd))[hc4] = h4;

    if (outlev == NLEV) {
        ((float4*)(out + OFF_ROOT + b * Hd))[hc4] = h4;
    } else {
        const size_t dst = (((size_t)(q >> 1) * Bt + b) * K2) + (q & 1) * Hd;
        ((float4*)(&g_A[cur ^ 1][dst]))[hc4] = h4;
        ((float4*)(&g_C[cur ^ 1][dst]))[hc4] = c4;
    }
}

// ---------------------------------------------------------------------------
// Launch
// ---------------------------------------------------------------------------
extern "C" void kernel_launch(void* const* d_in, const int* in_sizes, int n_in,
                              void* d_out, int out_size) {
    const int*   tok     = (const int*)d_in[0];
    const float* emb     = (const float*)d_in[1];
    const float* emb_aux = (const float*)d_in[2];
    const float* W       = (const float*)d_in[3];
    const float* bias    = (const float*)d_in[4];
    float*       out     = (float*)d_out;

    const int TH = 256;

    gather_kernel<<<(Lf * Bt * (Hd / 4) + TH - 1) / TH, TH>>>(
        tok, (const float4*)emb, (const float4*)emb_aux, out);

    mask_kernel<<<(255 * Bt + Lf * Bt + TH - 1) / TH, TH>>>(out);

    int n = Lf;
    for (int l = 0; l < NLEV; ++l) {
        const int n2 = n >> 1;
        const int M  = n2 * Bt;
        dim3 grid(N5 / BN, M / BM);
        gemm_kernel<<<grid, TH>>>(W, M, l & 1);

        const int tot = n2 << 15;    // n2 * Bt * (Hd/4) float4 lanes
        gates_kernel<<<(tot + TH - 1) / TH, TH>>>(
            (const float4*)bias, out, l, n2, l & 1);
        n = n2;
    }
}

// round 11
// speedup vs baseline: 2.0087x; 2.0087x over previous
#include <cuda_runtime.h>
#include <cuda_bf16.h>
#include <cstdint>

// ---------------------------------------------------------------------------
// TreeRNN: complete binary tree LSTM over 128 leaves, batch 512, hidden 256.
// GEMM on tensor cores via base-PTX mma.sync.m16n8k16.bf16 (tcgen05 is not
// assemblable: harness targets compute_103, not sm_103a). fp32 accuracy
// recovered with 2-term bf16 split (hi*hi + hi*lo + lo*hi).
// Fragment layouts desk-verified against PTX m16n8k16 operand maps (R6/R7).
// ---------------------------------------------------------------------------

#define Hd   256
#define Bt   512
#define Lf   128
#define K2   512      // 2*H
#define N5   1280     // 5*H
#define NLEV 7        // log2(Lf)

// Output buffer layout (flattened fp32, reference return order)
#define OFF_ROOT   0
#define OFF_INT    (Bt * Hd)
#define OFF_IMASK  (OFF_INT + 255 * Bt * Hd)
#define OFF_LEAVES (OFF_IMASK + 255 * Bt)
#define OFF_LAUX   (OFF_LEAVES + Lf * Bt * Hd)
#define OFF_LMASK  (OFF_LAUX + Lf * Bt * Hd)

// Scratch (device globals; no runtime allocation allowed)
__device__ float g_A[2][64 * Bt * K2];     // paired h, ping-pong (fp32)
__device__ float g_C[2][32 * Bt * K2];     // paired c, ping-pong
__device__ float g_G[32768 * N5];          // gate pre-activations
__device__ __nv_bfloat16 g_Wb_hi[N5 * K2]; // W^T bf16-hi  [1280][512]
__device__ __nv_bfloat16 g_Wb_lo[N5 * K2]; // W^T bf16-lo

__device__ __forceinline__ uint32_t smem_u32(const void* p) {
    uint32_t a;
    asm("{ .reg .u64 t; cvta.to.shared.u64 t, %1; cvt.u32.u64 %0, t; }"
        : "=r"(a) : "l"(p));
    return a;
}

// Post-order index of node (level, j); level 0 = leaves, level 7 = root.
__device__ __forceinline__ int post_idx(int level, int j) {
    int start = (1 << (level + 1)) - 2;
    for (int m = level + 1; m <= NLEV; ++m)
        start += ((j >> (m - 1 - level)) & 1) ? ((1 << m) - 1) : 0;
    return start;
}
__device__ __forceinline__ float sigf(float x) { return 1.0f / (1.0f + __expf(-x)); }

// ---------------------------------------------------------------------------
// W transpose + bf16 hi/lo split: W[512][1280] -> Wb_hi/lo[1280][512]
// ---------------------------------------------------------------------------
__global__ void wsplit_kernel(const float* __restrict__ W) {
    int idx = blockIdx.x * blockDim.x + threadIdx.x;
    if (idx >= K2 * N5) return;
    int n = idx % N5;
    int k = idx / N5;
    float w = W[idx];
    __nv_bfloat16 hi = __float2bfloat16_rn(w);
    __nv_bfloat16 lo = __float2bfloat16_rn(w - __bfloat162float(hi));
    g_Wb_hi[(size_t)n * K2 + k] = hi;
    g_Wb_lo[(size_t)n * K2 + k] = lo;
}

// ---------------------------------------------------------------------------
// Gather + masks (unchanged from the 1814us passing kernel)
// ---------------------------------------------------------------------------
__global__ void gather_kernel(const int* __restrict__ tok,
                              const float4* __restrict__ emb,
                              const float4* __restrict__ emb_aux,
                              float* __restrict__ out) {
    int idx = blockIdx.x * blockDim.x + threadIdx.x;
    if (idx >= Lf * Bt * (Hd / 4)) return;
    const int hc4 = idx & 63;
    const int b   = (idx >> 6) & (Bt - 1);
    const int j   = idx >> 15;

    const int t = tok[j * Bt + b];
    const float4 v  = emb[t * (Hd / 4) + hc4];
    const float4 va = emb_aux[t * (Hd / 4) + hc4];

    ((float4*)(out + OFF_LEAVES))[idx] = v;
    ((float4*)(out + OFF_LAUX))[idx]   = va;

    const int p = post_idx(0, j);
    ((float4*)(out + OFF_INT + ((size_t)p * Bt + b) * Hd))[hc4] = v;

    const size_t dst = (((size_t)(j >> 1) * Bt + b) * K2) + (j & 1) * Hd;
    ((float4*)(&g_A[0][dst]))[hc4] = v;
}

__global__ void mask_kernel(float* __restrict__ out) {
    int idx = blockIdx.x * blockDim.x + threadIdx.x;
    const int NI = 255 * Bt;
    const int NL = Lf * Bt;
    if (idx < NI)            out[OFF_IMASK + idx] = 1.0f;
    else if (idx < NI + NL)  out[OFF_LMASK + (idx - NI)] = 1.0f;
}

// ---------------------------------------------------------------------------
// Tensor-core GEMM: G[M,1280] = A[M,512] @ W[512,1280], bf16 split (3 mma).
// CTA 128x128, 8 warps (2x4), warp tile 64x32, K-chunk 64, double-buffered.
// A: fp32 gmem -> reg prefetch -> split to bf16 hi/lo -> swizzled smem.
// B: bf16 hi/lo gmem (pre-split) -> cp.async -> swizzled smem.
// Fragments via ldmatrix.x4; mma.sync.m16n8k16.row.col.f32.bf16.bf16.f32.
// SMEM tile: [128 rows][64 bf16 = 128B], 16B-chunk swizzle c ^= (row & 7).
// ---------------------------------------------------------------------------
#define TILE16K 16384
#define A_HI(buf) ((buf) * 65536 + 0)
#define A_LO(buf) ((buf) * 65536 + TILE16K)
#define B_HI(buf) ((buf) * 65536 + 2 * TILE16K)
#define B_LO(buf) ((buf) * 65536 + 3 * TILE16K)
#define SMEM_GEMM 131072

#define LDSM_X4(d0, d1, d2, d3, addr)                                         \
    asm volatile("ldmatrix.sync.aligned.m8n8.x4.shared.b16 {%0,%1,%2,%3}, [%4];" \
                 : "=r"(d0), "=r"(d1), "=r"(d2), "=r"(d3) : "r"(addr))

#define MMA_BF16(c, a, b)                                                     \
    asm volatile("mma.sync.aligned.m16n8k16.row.col.f32.bf16.bf16.f32 "       \
                 "{%0,%1,%2,%3}, {%4,%5,%6,%7}, {%8,%9}, {%0,%1,%2,%3};"      \
                 : "+f"((c)[0]), "+f"((c)[1]), "+f"((c)[2]), "+f"((c)[3])     \
                 : "r"((a)[0]), "r"((a)[1]), "r"((a)[2]), "r"((a)[3]),        \
                   "r"((b)[0]), "r"((b)[1]))

#define CP_ASYNC16(dst, src)                                                  \
    asm volatile("cp.async.cg.shared.global [%0], [%1], 16;"                  \
                 :: "r"(dst), "l"(src) : "memory")

__global__ void __launch_bounds__(256, 1)
tc_gemm_kernel(int cur) {
    extern __shared__ char smem[];
    const uint32_t sb = smem_u32(smem);
    const int tid  = threadIdx.x;
    const int lane = tid & 31;
    const int wid  = tid >> 5;
    const int wm   = wid >> 2;         // 0..1  (m-warp)
    const int wn   = wid & 3;          // 0..3  (n-warp)

    const int bm = blockIdx.y * 128;
    const int bn = blockIdx.x * 128;
    const float* __restrict__ A = g_A[cur] + (size_t)bm * K2;

    float acc[4][4][4];
#pragma unroll
    for (int i = 0; i < 4; i++)
#pragma unroll
        for (int j = 0; j < 4; j++) {
            acc[i][j][0] = 0.f; acc[i][j][1] = 0.f;
            acc[i][j][2] = 0.f; acc[i][j][3] = 0.f;
        }

    // staging granule coords: 1024 granules of 16B-bf16 (=8 elems) per tile
    // gid = tid + 256*i : r = gid>>3 (row), cc = gid&7 (16B chunk)
    float aR[32];   // A prefetch: 4 granules x 8 fp32

#define STAGE_B(ch, buf) do {                                                 \
    _Pragma("unroll")                                                         \
    for (int i = 0; i < 4; i++) {                                             \
        int gid = tid + 256 * i;                                              \
        int r = gid >> 3, cc = gid & 7;                                       \
        size_t go = (size_t)(bn + r) * K2 + (ch) * 64 + cc * 8;               \
        uint32_t so = r * 128 + ((cc ^ (r & 7)) << 4);                        \
        CP_ASYNC16(sb + B_HI(buf) + so, (const char*)(g_Wb_hi + go));         \
        CP_ASYNC16(sb + B_LO(buf) + so, (const char*)(g_Wb_lo + go));         \
    }                                                                         \
    asm volatile("cp.async.commit_group;" ::: "memory");                      \
} while (0)

#define LDG_A(ch) do {                                                        \
    _Pragma("unroll")                                                         \
    for (int i = 0; i < 4; i++) {                                             \
        int gid = tid + 256 * i;                                              \
        int r = gid >> 3, cc = gid & 7;                                       \
        const float* src = A + (size_t)r * K2 + (ch) * 64 + cc * 8;           \
        float4 v0 = *(const float4*)src;                                      \
        float4 v1 = *(const float4*)(src + 4);                                \
        aR[i*8+0] = v0.x; aR[i*8+1] = v0.y; aR[i*8+2] = v0.z; aR[i*8+3] = v0.w;\
        aR[i*8+4] = v1.x; aR[i*8+5] = v1.y; aR[i*8+6] = v1.z; aR[i*8+7] = v1.w;\
    }                                                                         \
} while (0)

#define STS_A(buf) do {                                                       \
    _Pragma("unroll")                                                         \
    for (int i = 0; i < 4; i++) {                                             \
        int gid = tid + 256 * i;                                              \
        int r = gid >> 3, cc = gid & 7;                                       \
        uint32_t hiU[4], loU[4];                                              \
        _Pragma("unroll")                                                     \
        for (int p = 0; p < 4; p++) {                                         \
            float x = aR[i*8 + 2*p], y = aR[i*8 + 2*p + 1];                   \
            __nv_bfloat162 h2 = __floats2bfloat162_rn(x, y);                  \
            float hx = __low2float(h2), hy = __high2float(h2);                \
            __nv_bfloat162 l2 = __floats2bfloat162_rn(x - hx, y - hy);        \
            hiU[p] = *(uint32_t*)&h2;                                         \
            loU[p] = *(uint32_t*)&l2;                                         \
        }                                                                     \
        uint32_t so = r * 128 + ((cc ^ (r & 7)) << 4);                        \
        *(uint4*)(smem + A_HI(buf) + so) = make_uint4(hiU[0],hiU[1],hiU[2],hiU[3]); \
        *(uint4*)(smem + A_LO(buf) + so) = make_uint4(loU[0],loU[1],loU[2],loU[3]); \
    }                                                                         \
} while (0)

    // ---- prologue: chunk 0 into buffer 0 ----
    STAGE_B(0, 0);
    LDG_A(0);
    STS_A(0);
    asm volatile("cp.async.wait_group 0;" ::: "memory");
    __syncthreads();

    int buf = 0;
    for (int ch = 0; ch < 8; ++ch) {
        const bool nxt = (ch + 1) < 8;
        if (nxt) {
            STAGE_B(ch + 1, buf ^ 1);
            LDG_A(ch + 1);
        }

        // compute 4 ksteps (k16 each) on current buffer
#pragma unroll
        for (int ks = 0; ks < 4; ++ks) {
            uint32_t aH[4][4], aL[4][4], bH[4][2], bL[4][2];
#pragma unroll
            for (int mf = 0; mf < 4; mf++) {
                int r = wm * 64 + mf * 16 + (lane & 15);
                int c = ks * 2 + (lane >> 4);
                uint32_t so = r * 128 + ((c ^ (r & 7)) << 4);
                LDSM_X4(aH[mf][0], aH[mf][1], aH[mf][2], aH[mf][3], sb + A_HI(buf) + so);
                LDSM_X4(aL[mf][0], aL[mf][1], aL[mf][2], aL[mf][3], sb + A_LO(buf) + so);
            }
#pragma unroll
            for (int nf2 = 0; nf2 < 2; nf2++) {
                int n = wn * 32 + nf2 * 16 + (lane & 7) + ((lane >> 4) << 3);
                int c = ks * 2 + ((lane >> 3) & 1);
                uint32_t so = n * 128 + ((c ^ (n & 7)) << 4);
                LDSM_X4(bH[2*nf2][0], bH[2*nf2][1], bH[2*nf2+1][0], bH[2*nf2+1][1],
                        sb + B_HI(buf) + so);
                LDSM_X4(bL[2*nf2][0], bL[2*nf2][1], bL[2*nf2+1][0], bL[2*nf2+1][1],
                        sb + B_LO(buf) + so);
            }
#pragma unroll
            for (int mf = 0; mf < 4; mf++)
#pragma unroll
                for (int nf = 0; nf < 4; nf++) {
                    MMA_BF16(acc[mf][nf], aH[mf], bH[nf]);
                    MMA_BF16(acc[mf][nf], aH[mf], bL[nf]);
                    MMA_BF16(acc[mf][nf], aL[mf], bH[nf]);
                }
        }

        if (nxt) {
            STS_A(buf ^ 1);
            asm volatile("cp.async.wait_group 0;" ::: "memory");
            __syncthreads();
            buf ^= 1;
        }
    }

    // epilogue: write fp32 accumulators to g_G
#pragma unroll
    for (int mf = 0; mf < 4; mf++) {
        int r0 = bm + wm * 64 + mf * 16 + (lane >> 2);
        int r1 = r0 + 8;
#pragma unroll
        for (int nf = 0; nf < 4; nf++) {
            int col = bn + wn * 32 + nf * 8 + (lane & 3) * 2;
            *(float2*)(g_G + (size_t)r0 * N5 + col) =
                make_float2(acc[mf][nf][0], acc[mf][nf][1]);
            *(float2*)(g_G + (size_t)r1 * N5 + col) =
                make_float2(acc[mf][nf][2], acc[mf][nf][3]);
        }
    }
#undef STAGE_B
#undef LDG_A
#undef STS_A
}

// ---------------------------------------------------------------------------
// Gates (unchanged): bias + LSTM combine, float4 lanes
// ---------------------------------------------------------------------------
__global__ void gates_kernel(const float4* __restrict__ bias4,
                             float* __restrict__ out,
                             int level, int n2, int cur) {
    int idx = blockIdx.x * blockDim.x + threadIdx.x;
    if (idx >= (n2 << 15)) return;
    const int hc4 = idx & 63;
    const int b   = (idx >> 6) & (Bt - 1);
    const int q   = idx >> 15;

    const float4* __restrict__ g4 = (const float4*)(g_G + ((size_t)q * Bt + b) * N5);
    const float4 gi  = g4[hc4];
    const float4 gf1 = g4[64  + hc4];
    const float4 gf2 = g4[128 + hc4];
    const float4 go  = g4[192 + hc4];
    const float4 gu  = g4[256 + hc4];
    const float4 bi  = bias4[hc4];
    const float4 bf1 = bias4[64  + hc4];
    const float4 bf2 = bias4[128 + hc4];
    const float4 bo  = bias4[192 + hc4];
    const float4 bu  = bias4[256 + hc4];

    float4 cL = make_float4(0.f, 0.f, 0.f, 0.f);
    float4 cR = cL;
    if (level > 0) {
        const float4* __restrict__ C4 =
            (const float4*)(g_C[cur] + ((size_t)q * Bt + b) * K2);
        cL = C4[hc4];
        cR = C4[64 + hc4];
    }

    float i_[4]  = {gi.x + bi.x,  gi.y + bi.y,  gi.z + bi.z,  gi.w + bi.w};
    float f1[4]  = {gf1.x + bf1.x, gf1.y + bf1.y, gf1.z + bf1.z, gf1.w + bf1.w};
    float f2[4]  = {gf2.x + bf2.x, gf2.y + bf2.y, gf2.z + bf2.z, gf2.w + bf2.w};
    float o_[4]  = {go.x + bo.x,  go.y + bo.y,  go.z + bo.z,  go.w + bo.w};
    float u_[4]  = {gu.x + bu.x,  gu.y + bu.y,  gu.z + bu.z,  gu.w + bu.w};
    float cl[4]  = {cL.x, cL.y, cL.z, cL.w};
    float cr[4]  = {cR.x, cR.y, cR.z, cR.w};
    float hv[4], cv[4];
#pragma unroll
    for (int e = 0; e < 4; e++) {
        float c = sigf(i_[e]) * tanhf(u_[e]);
        if (level > 0)
            c += sigf(f1[e]) * cl[e] + sigf(f2[e]) * cr[e];
        hv[e] = sigf(o_[e]) * tanhf(c);
        cv[e] = c;
    }
    float4 h4 = make_float4(hv[0], hv[1], hv[2], hv[3]);
    float4 c4 = make_float4(cv[0], cv[1], cv[2], cv[3]);

    const int outlev = level + 1;
    const int p = post_idx(outlev, q);
    ((float4*)(out + OFF_INT + ((size_t)p * Bt + b) * Hd))[hc4] = h4;

    if (outlev == NLEV) {
        ((float4*)(out + OFF_ROOT + b * Hd))[hc4] = h4;
    } else {
        const size_t dst = (((size_t)(q >> 1) * Bt + b) * K2) + (q & 1) * Hd;
        ((float4*)(&g_A[cur ^ 1][dst]))[hc4] = h4;
        ((float4*)(&g_C[cur ^ 1][dst]))[hc4] = c4;
    }
}

// ---------------------------------------------------------------------------
// Launch
// ---------------------------------------------------------------------------
extern "C" void kernel_launch(void* const* d_in, const int* in_sizes, int n_in,
                              void* d_out, int out_size) {
    const int*   tok     = (const int*)d_in[0];
    const float* emb     = (const float*)d_in[1];
    const float* emb_aux = (const float*)d_in[2];
    const float* W       = (const float*)d_in[3];
    const float* bias    = (const float*)d_in[4];
    float*       out     = (float*)d_out;

    const int TH = 256;

    cudaFuncSetAttribute(tc_gemm_kernel,
                         cudaFuncAttributeMaxDynamicSharedMemorySize, SMEM_GEMM);

    wsplit_kernel<<<(K2 * N5 + TH - 1) / TH, TH>>>(W);

    gather_kernel<<<(Lf * Bt * (Hd / 4) + TH - 1) / TH, TH>>>(
        tok, (const float4*)emb, (const float4*)emb_aux, out);

    mask_kernel<<<(255 * Bt + Lf * Bt + TH - 1) / TH, TH>>>(out);

    int n = Lf;
    for (int l = 0; l < NLEV; ++l) {
        const int n2 = n >> 1;
        dim3 grid(N5 / 128, n2 * Bt / 128);
        tc_gemm_kernel<<<grid, TH, SMEM_GEMM>>>(l & 1);

        const int tot = n2 << 15;
        gates_kernel<<<(tot + TH - 1) / TH, TH>>>(
            (const float4*)bias, out, l, n2, l & 1);
        n = n2;
    }
}